// round 11
// baseline (speedup 1.0000x reference)
#include <cuda_runtime.h>
#include <cuda_bf16.h>
#include <cstdint>

#define H_HOPS   100000
#define MAX_PI   8
#define D        128
#define D_FF     512
#define TT       64
#define LN_EPS   1e-5f
#define TILE_M   128
#define NCHUNK   8
#define NTILES   782            /* ceil(100000/128) */
#define PGRID    148
#define PREP_BLOCKS 64

// ---- smem map (bytes) ----
#define XS_HI   0u            /* 128 x 136 bf16 = 34816 ; reused as f32 reduce buf */
#define XS_LO   34816u
#define BUF0    69632u
#define BUFSZ   53248u        /* W1H 17408 | W1L 17408 | WGH 9216 | WGL 9216 */
#define W1L_OFF 17408u
#define WGH_OFF 34816u
#define WGL_OFF 44032u
#define B1S     176128u       /* 512 f32 */
#define USOFF   178176u       /* 64 f32 */
#define VSOFF   178432u
#define SRED    178688u       /* 2 x 128 f32 */
#define QRED    179712u       /* 2 x 128 f32 */
#define MB0     180736u
#define MB1     180744u
#define MBX     180752u
#define SMEM_SZ 180768u

#define RSTRIDE 66            /* f32 stride of reduce buffer */

// ---- device scratch ----
__device__ __align__(16) __nv_bfloat16 g_B1hi[NCHUNK * 64 * 136];
__device__ __align__(16) __nv_bfloat16 g_B1lo[NCHUNK * 64 * 136];
__device__ __align__(16) __nv_bfloat16 g_B2hi[NCHUNK * 64 * 72];
__device__ __align__(16) __nv_bfloat16 g_B2lo[NCHUNK * 64 * 72];
__device__ float g_u[TT];
__device__ float g_v[TT];
// pre-split pooled X, tile-contiguous smem image (17408 bf16 per tile)
__device__ __align__(16) __nv_bfloat16 g_XShi[NTILES * 17408];
__device__ __align__(16) __nv_bfloat16 g_XSlo[NTILES * 17408];

// ---- helpers ----
__device__ __forceinline__ unsigned smem_u32(const void* p) {
    return (unsigned)__cvta_generic_to_shared(p);
}
__device__ __forceinline__ uint32_t elect_one() {
    uint32_t p;
    asm volatile("{\n\t.reg .pred q;\n\telect.sync _|q, 0xFFFFFFFF;\n\t"
                 "selp.b32 %0, 1, 0, q;\n\t}" : "=r"(p));
    return p;
}
__device__ __forceinline__ unsigned cvt_bf16x2(float hi, float lo) {
    unsigned r;
    asm("cvt.rn.bf16x2.f32 %0, %1, %2;" : "=r"(r) : "f"(hi), "f"(lo));
    return r;
}
__device__ __forceinline__ float bf_lo(unsigned w) { return __uint_as_float(w << 16); }
__device__ __forceinline__ float bf_hi(unsigned w) { return __uint_as_float(w & 0xffff0000u); }
__device__ __forceinline__ void sts64(unsigned a, unsigned u0, unsigned u1) {
    asm volatile("st.shared.v2.b32 [%0], {%1, %2};" :: "r"(a), "r"(u0), "r"(u1) : "memory");
}
__device__ __forceinline__ void ldsm_x4(unsigned* r, unsigned a) {
    asm volatile("ldmatrix.sync.aligned.m8n8.x4.shared.b16 {%0,%1,%2,%3}, [%4];"
                 : "=r"(r[0]), "=r"(r[1]), "=r"(r[2]), "=r"(r[3]) : "r"(a));
}
__device__ __forceinline__ void ldsm_x2(unsigned* r, unsigned a) {
    asm volatile("ldmatrix.sync.aligned.m8n8.x2.shared.b16 {%0,%1}, [%2];"
                 : "=r"(r[0]), "=r"(r[1]) : "r"(a));
}
__device__ __forceinline__ void mma16816(float* d, const unsigned* a,
                                         unsigned b0, unsigned b1) {
    asm volatile(
        "mma.sync.aligned.m16n8k16.row.col.f32.bf16.bf16.f32 "
        "{%0,%1,%2,%3}, {%4,%5,%6,%7}, {%8,%9}, {%0,%1,%2,%3};"
        : "+f"(d[0]), "+f"(d[1]), "+f"(d[2]), "+f"(d[3])
        : "r"(a[0]), "r"(a[1]), "r"(a[2]), "r"(a[3]), "r"(b0), "r"(b1));
}

#define MBAR_INIT(a, c) \
    asm volatile("mbarrier.init.shared.b64 [%0], %1;" :: "r"(a), "r"(c) : "memory")
#define MBAR_EXPECT(a, b) \
    asm volatile("mbarrier.arrive.expect_tx.shared.b64 _, [%0], %1;" :: "r"(a), "r"(b) : "memory")
#define MBAR_WAIT(a, par) do {                                                  \
    asm volatile("{\n\t.reg .pred P1;\n\t"                                      \
        "WL_%=:\n\t"                                                            \
        "mbarrier.try_wait.parity.acquire.cta.shared::cta.b64 P1, [%0], %1, 0x989680;\n\t" \
        "@P1 bra.uni WD_%=;\n\tbra.uni WL_%=;\n\tWD_%=:\n\t}"                   \
        :: "r"(a), "r"(par) : "memory");                                        \
} while (0)
#define BULK_G2S(d, s, b, m) \
    asm volatile("cp.async.bulk.shared::cluster.global.mbarrier::complete_tx::bytes " \
                 "[%0], [%1], %2, [%3];" :: "r"(d), "l"(s), "r"(b), "r"(m) : "memory")
#define FENCE_PROXY_ASYNC() asm volatile("fence.proxy.async;" ::: "memory")

// ==================== prep: weight images + folded LN ====================
__global__ __launch_bounds__(256)
void prep_kernel(const float* __restrict__ W1, const float* __restrict__ gamma,
                 const float* __restrict__ beta, const float* __restrict__ W2,
                 const float* __restrict__ b2) {
    __shared__ float pu[256], pv[256];
    int g = blockIdx.x * 256 + threadIdx.x, gs = PREP_BLOCKS * 256;
    for (int i = g; i < D * D_FF; i += gs) {
        int k = i >> 9, n = i & 511;
        float val = W1[i];
        __nv_bfloat16 h = __float2bfloat16(val);
        __nv_bfloat16 lo = __float2bfloat16(val - __bfloat162float(h));
        int idx = (n >> 6) * (64 * 136) + (n & 63) * 136 + k;
        g_B1hi[idx] = h; g_B1lo[idx] = lo;
    }
    for (int i = g; i < D_FF * TT; i += gs) {
        int kf = i >> 6, n = i & 63;
        float val = gamma[kf] * W2[i];
        __nv_bfloat16 h = __float2bfloat16(val);
        __nv_bfloat16 lo = __float2bfloat16(val - __bfloat162float(h));
        int idx = (kf >> 6) * (64 * 72) + n * 72 + (kf & 63);
        g_B2hi[idx] = h; g_B2lo[idx] = lo;
    }
    if (blockIdx.x == 0) {
        int t = threadIdx.x & 63, part = threadIdx.x >> 6;
        float u = 0.f, v = 0.f;
        for (int c = part * 128; c < part * 128 + 128; c++) {
            float w2 = W2[c * TT + t];
            u += gamma[c] * w2; v += beta[c] * w2;
        }
        pu[threadIdx.x] = u; pv[threadIdx.x] = v;
        __syncthreads();
        if (threadIdx.x < 64) {
            float su = 0.f, sv = 0.f;
            for (int p = 0; p < 4; p++) { su += pu[p * 64 + t]; sv += pv[p * 64 + t]; }
            g_u[t] = su; g_v[t] = sv + b2[t];
        }
    }
}

// pool one hop row (warp-collective); returns this lane's float4 slice
__device__ __forceinline__ float4 pool_row(
    const float* __restrict__ hf, float4 wq,
    const int* __restrict__ pi, const int* __restrict__ stats,
    const int* __restrict__ po, int gr, int d0) {
    float4 acc = make_float4(0.f, 0.f, 0.f, 0.f);
    float4 tok[MAX_PI + 1]; float sc[MAX_PI + 1]; bool ok[MAX_PI + 1];
    #pragma unroll
    for (int p = 0; p <= MAX_PI; p++) {
        int idx; bool v;
        if (p < MAX_PI) { idx = pi[gr * MAX_PI + p]; v = (stats[gr * MAX_PI + p] != -1); }
        else            { idx = po[gr];              v = true; }
        float4 t = *reinterpret_cast<const float4*>(hf + (long long)idx * D + d0);
        tok[p] = t; ok[p] = v;
        float s = t.x * wq.x + t.y * wq.y + t.z * wq.z + t.w * wq.w;
        #pragma unroll
        for (int o = 16; o; o >>= 1) s += __shfl_xor_sync(0xffffffffu, s, o);
        sc[p] = s * 0.08838834764831845f;
    }
    float m = -1e30f;
    #pragma unroll
    for (int p = 0; p <= MAX_PI; p++) if (ok[p] && sc[p] > m) m = sc[p];
    float den = 0.f;
    #pragma unroll
    for (int p = 0; p <= MAX_PI; p++) {
        float e = ok[p] ? __expf(sc[p] - m) : 0.f;
        den += e;
        acc.x += e * tok[p].x; acc.y += e * tok[p].y;
        acc.z += e * tok[p].z; acc.w += e * tok[p].w;
    }
    float inv = 1.f / den;
    acc.x *= inv; acc.y *= inv; acc.z *= inv; acc.w *= inv;
    return acc;
}

// ====== persistent fused head: pipelined pooling + 16-warp N-split mma.sync ======
__global__ __launch_bounds__(512, 1)
void head_kernel(const float* __restrict__ hf, const float* __restrict__ w_q,
                 const int* __restrict__ pi, const int* __restrict__ stats,
                 const int* __restrict__ po,
                 const float* __restrict__ b1, float* __restrict__ out) {
    extern __shared__ char smem[];
    const unsigned sb = smem_u32(smem);
    int tid = threadIdx.x, w = tid >> 5, lane = tid & 31;
    int wm = w & 7, g2 = w >> 3;
    int grp = lane >> 2, q = lane & 3;
    int LL = lane & 15;
    int m0 = wm * 16;
    int bid = blockIdx.x;
    int ntm = (NTILES - bid + PGRID - 1) / PGRID;   // tiles for this CTA
    int NG = ntm * NCHUNK;

    if (tid == 0) { MBAR_INIT(sb + MB0, 1); MBAR_INIT(sb + MB1, 1); MBAR_INIT(sb + MBX, 1); }
    __syncthreads();

    if (w == 0 && elect_one()) {          // prefetch global chunks G=0,1
        MBAR_EXPECT(sb + MB0, BUFSZ);
        BULK_G2S(sb + BUF0,           (const void*)(g_B1hi), 17408u, sb + MB0);
        BULK_G2S(sb + BUF0 + W1L_OFF, (const void*)(g_B1lo), 17408u, sb + MB0);
        BULK_G2S(sb + BUF0 + WGH_OFF, (const void*)(g_B2hi), 9216u,  sb + MB0);
        BULK_G2S(sb + BUF0 + WGL_OFF, (const void*)(g_B2lo), 9216u,  sb + MB0);
        MBAR_EXPECT(sb + MB1, BUFSZ);
        BULK_G2S(sb + BUF0 + BUFSZ,            (const void*)(g_B1hi + 8704), 17408u, sb + MB1);
        BULK_G2S(sb + BUF0 + BUFSZ + W1L_OFF,  (const void*)(g_B1lo + 8704), 17408u, sb + MB1);
        BULK_G2S(sb + BUF0 + BUFSZ + WGH_OFF,  (const void*)(g_B2hi + 4608), 9216u,  sb + MB1);
        BULK_G2S(sb + BUF0 + BUFSZ + WGL_OFF,  (const void*)(g_B2lo + 4608), 9216u,  sb + MB1);
    }

    float* b1s = (float*)(smem + B1S);
    for (int i = tid; i < D_FF; i += 512) b1s[i] = b1[i];
    if (tid < TT) {
        ((float*)(smem + USOFF))[tid] = g_u[tid];
        ((float*)(smem + VSOFF))[tid] = g_v[tid];
    }
    int d0 = lane * 4;
    float4 wq = *reinterpret_cast<const float4*>(w_q + d0);

    // ---- inline-pool FIRST tile into XS ----
    {
        int row0 = bid * TILE_M;
        #pragma unroll 1
        for (int i = 0; i < 8; i++) {
            int r = w * 8 + i, gr = row0 + r;
            float4 acc = make_float4(0.f, 0.f, 0.f, 0.f);
            if (gr < H_HOPS) acc = pool_row(hf, wq, pi, stats, po, gr, d0);
            unsigned h0 = cvt_bf16x2(acc.y, acc.x), h1 = cvt_bf16x2(acc.w, acc.z);
            unsigned a = sb + XS_HI + (unsigned)(r * 272 + d0 * 2);
            sts64(a, h0, h1);
            float e0 = acc.x - bf_lo(h0), e1 = acc.y - bf_hi(h0);
            float e2 = acc.z - bf_lo(h1), e3 = acc.w - bf_hi(h1);
            sts64(a + XS_LO, cvt_bf16x2(e1, e0), cvt_bf16x2(e3, e2));
        }
    }
    __syncthreads();

    const unsigned abase  = sb + XS_HI + (unsigned)((m0 + LL) * 272 + (lane >> 4) * 16);
    const unsigned bgeom1 = (unsigned)((LL & 7) * 272 + ((LL >> 3) & 1) * 16);
    const unsigned bgeom2 = (unsigned)((LL & 7) * 144 + ((LL >> 3) & 1) * 16);

    for (int it = 0; it < ntm; it++) {
        int tile = bid + PGRID * it;
        int row0 = tile * TILE_M;
        int tileN = tile + PGRID;
        bool haveNext = (tileN < NTILES);

        if (it > 0) MBAR_WAIT(sb + MBX, (unsigned)((it - 1) & 1));  // XS resident

        float acc2[32];
        #pragma unroll
        for (int i = 0; i < 32; i++) acc2[i] = 0.f;
        float s0 = 0.f, q0 = 0.f, s1 = 0.f, q1 = 0.f;

        for (int c = 0; c < NCHUNK; c++) {
            int G = it * NCHUNK + c;
            unsigned bb_ = sb + BUF0 + (unsigned)((G & 1) * BUFSZ);
            MBAR_WAIT(sb + MB0 + 8u * (unsigned)(G & 1), (unsigned)((G >> 1) & 1));

            float acc1[16];
            #pragma unroll
            for (int i = 0; i < 16; i++) acc1[i] = 0.f;
            unsigned b1base = bb_ + bgeom1 + (unsigned)(g2 * 4 * 2176);

            #pragma unroll
            for (int s = 0; s < 8; s++) {
                unsigned Ah[4], Al[4];
                ldsm_x4(Ah, abase + (unsigned)(s * 32));
                ldsm_x4(Al, abase + XS_LO + (unsigned)(s * 32));
                #pragma unroll
                for (int j2 = 0; j2 < 4; j2++) {
                    unsigned Bh[2], Bl[2];
                    unsigned ba = b1base + (unsigned)(j2 * 2176 + s * 32);
                    ldsm_x2(Bh, ba);
                    ldsm_x2(Bl, ba + W1L_OFF);
                    mma16816(acc1 + 4 * j2, Ah, Bh[0], Bh[1]);
                    mma16816(acc1 + 4 * j2, Ah, Bl[0], Bl[1]);
                    mma16816(acc1 + 4 * j2, Al, Bh[0], Bh[1]);
                }
            }

            // bias + relu + LN partials + register repack
            unsigned A2h[8], A2l[8];
            #pragma unroll
            for (int j2 = 0; j2 < 4; j2++) {
                int col = c * 64 + g2 * 32 + 8 * j2 + 2 * q;
                float2 bb = *(const float2*)(smem + B1S + col * 4);
                float h0 = fmaxf(acc1[4 * j2 + 0] + bb.x, 0.f);
                float h1 = fmaxf(acc1[4 * j2 + 1] + bb.y, 0.f);
                float h2 = fmaxf(acc1[4 * j2 + 2] + bb.x, 0.f);
                float h3 = fmaxf(acc1[4 * j2 + 3] + bb.y, 0.f);
                s0 += h0 + h1; q0 = fmaf(h0, h0, fmaf(h1, h1, q0));
                s1 += h2 + h3; q1 = fmaf(h2, h2, fmaf(h3, h3, q1));
                unsigned p0 = cvt_bf16x2(h1, h0), p1 = cvt_bf16x2(h3, h2);
                int bi = (j2 >> 1) * 4 + (j2 & 1) * 2;
                A2h[bi] = p0; A2h[bi + 1] = p1;
                float e0 = h0 - bf_lo(p0), e1 = h1 - bf_hi(p0);
                float e2 = h2 - bf_lo(p1), e3 = h3 - bf_hi(p1);
                A2l[bi] = cvt_bf16x2(e1, e0); A2l[bi + 1] = cvt_bf16x2(e3, e2);
            }

            // GEMM2 partial
            unsigned g2base = bb_ + WGH_OFF + bgeom2;
            #pragma unroll
            for (int t = 0; t < 2; t++) {
                #pragma unroll
                for (int jn = 0; jn < 8; jn++) {
                    unsigned Bh[2], Bl[2];
                    unsigned ba = g2base + (unsigned)(jn * 1152 + (g2 * 2 + t) * 32);
                    ldsm_x2(Bh, ba);
                    ldsm_x2(Bl, ba + 9216);
                    mma16816(acc2 + 4 * jn, A2h + 4 * t, Bh[0], Bh[1]);
                    mma16816(acc2 + 4 * jn, A2h + 4 * t, Bl[0], Bl[1]);
                    mma16816(acc2 + 4 * jn, A2l + 4 * t, Bh[0], Bh[1]);
                }
            }

            // pipelined pooling: one row of NEXT tile per chunk -> global split image
            if (haveNext) {
                int r = w * 8 + c, gr = tileN * TILE_M + r;
                float4 acc = make_float4(0.f, 0.f, 0.f, 0.f);
                if (gr < H_HOPS) acc = pool_row(hf, wq, pi, stats, po, gr, d0);
                unsigned h0 = cvt_bf16x2(acc.y, acc.x), h1 = cvt_bf16x2(acc.w, acc.z);
                float e0 = acc.x - bf_lo(h0), e1 = acc.y - bf_hi(h0);
                float e2 = acc.z - bf_lo(h1), e3 = acc.w - bf_hi(h1);
                size_t gbase = (size_t)tileN * 4352 + r * 34 + lane;
                ((uint2*)g_XShi)[gbase] = make_uint2(h0, h1);
                ((uint2*)g_XSlo)[gbase] = make_uint2(cvt_bf16x2(e1, e0), cvt_bf16x2(e3, e2));
            }
            __syncthreads();
            if (G + 2 < NG && w == 0 && elect_one()) {
                int cc = (G + 2) & 7;
                unsigned mb = sb + MB0 + 8u * (unsigned)(G & 1);
                MBAR_EXPECT(mb, BUFSZ);
                BULK_G2S(bb_,           (const void*)(g_B1hi + cc * 8704), 17408u, mb);
                BULK_G2S(bb_ + W1L_OFF, (const void*)(g_B1lo + cc * 8704), 17408u, mb);
                BULK_G2S(bb_ + WGH_OFF, (const void*)(g_B2hi + cc * 4608), 9216u,  mb);
                BULK_G2S(bb_ + WGL_OFF, (const void*)(g_B2lo + cc * 4608), 9216u,  mb);
            }
        }

        // LN partials
        s0 += __shfl_xor_sync(0xffffffffu, s0, 1); s0 += __shfl_xor_sync(0xffffffffu, s0, 2);
        q0 += __shfl_xor_sync(0xffffffffu, q0, 1); q0 += __shfl_xor_sync(0xffffffffu, q0, 2);
        s1 += __shfl_xor_sync(0xffffffffu, s1, 1); s1 += __shfl_xor_sync(0xffffffffu, s1, 2);
        q1 += __shfl_xor_sync(0xffffffffu, q1, 1); q1 += __shfl_xor_sync(0xffffffffu, q1, 2);
        float* sred = (float*)(smem + SRED);
        float* qred = (float*)(smem + QRED);
        if (q == 0) {
            sred[g2 * 128 + m0 + grp]     = s0;  qred[g2 * 128 + m0 + grp]     = q0;
            sred[g2 * 128 + m0 + grp + 8] = s1;  qred[g2 * 128 + m0 + grp + 8] = q1;
        }
        __syncthreads();

        // cross-half acc2 reduce through XS region
        float* red = (float*)(smem + XS_HI);
        if (g2 == 1) {
            #pragma unroll
            for (int jn = 0; jn < 8; jn++) {
                int col = 8 * jn + 2 * q;
                *(float2*)(red + (m0 + grp) * RSTRIDE + col) =
                    make_float2(acc2[4 * jn + 0], acc2[4 * jn + 1]);
                *(float2*)(red + (m0 + grp + 8) * RSTRIDE + col) =
                    make_float2(acc2[4 * jn + 2], acc2[4 * jn + 3]);
            }
        }
        __syncthreads();
        if (g2 == 0) {
            float sA = sred[m0 + grp] + sred[128 + m0 + grp];
            float qA = qred[m0 + grp] + qred[128 + m0 + grp];
            float sB = sred[m0 + grp + 8] + sred[128 + m0 + grp + 8];
            float qB = qred[m0 + grp + 8] + qred[128 + m0 + grp + 8];
            float muA = sA * (1.f / D_FF), muB = sB * (1.f / D_FF);
            float rsA = rsqrtf(qA * (1.f / D_FF) - muA * muA + LN_EPS);
            float rsB = rsqrtf(qB * (1.f / D_FF) - muB * muB + LN_EPS);
            int ra = row0 + m0 + grp, rb = ra + 8;
            #pragma unroll
            for (int jn = 0; jn < 8; jn++) {
                int col = 8 * jn + 2 * q;
                float2 uu = *(const float2*)(smem + USOFF + col * 4);
                float2 vv = *(const float2*)(smem + VSOFF + col * 4);
                float2 pA = *(const float2*)(red + (m0 + grp) * RSTRIDE + col);
                float2 pB = *(const float2*)(red + (m0 + grp + 8) * RSTRIDE + col);
                if (ra < H_HOPS) {
                    float2 o;
                    o.x = rsA * (acc2[4 * jn + 0] + pA.x - muA * uu.x) + vv.x;
                    o.y = rsA * (acc2[4 * jn + 1] + pA.y - muA * uu.y) + vv.y;
                    *(float2*)(out + (size_t)ra * TT + col) = o;
                }
                if (rb < H_HOPS) {
                    float2 o;
                    o.x = rsB * (acc2[4 * jn + 2] + pB.x - muB * uu.x) + vv.x;
                    o.y = rsB * (acc2[4 * jn + 3] + pB.y - muB * uu.y) + vv.y;
                    *(float2*)(out + (size_t)rb * TT + col) = o;
                }
            }
        }

        if (it + 1 < ntm) {
            __threadfence();               // pooled STGs -> visible
            __syncthreads();               // red reads done; stores ordered
            if (w == 0 && elect_one()) {
                FENCE_PROXY_ASYNC();
                MBAR_EXPECT(sb + MBX, 69632u);
                BULK_G2S(sb + XS_HI, (const void*)(g_XShi + (size_t)tileN * 17408), 34816u, sb + MBX);
                BULK_G2S(sb + XS_LO, (const void*)(g_XSlo + (size_t)tileN * 17408), 34816u, sb + MBX);
            }
        }
    }
}

extern "C" void kernel_launch(void* const* d_in, const int* in_sizes, int n_in,
                              void* d_out, int out_size) {
    const float* hf    = (const float*)d_in[0];
    const float* w_q   = (const float*)d_in[1];
    const float* W1    = (const float*)d_in[2];
    const float* b1    = (const float*)d_in[3];
    const float* gamma = (const float*)d_in[4];
    const float* beta  = (const float*)d_in[5];
    const float* W2    = (const float*)d_in[6];
    const float* b2    = (const float*)d_in[7];
    const int* pi      = (const int*)d_in[8];
    const int* stats   = (const int*)d_in[9];
    const int* po      = (const int*)d_in[10];
    float* out = (float*)d_out;

    cudaFuncSetAttribute(head_kernel,
                         cudaFuncAttributeMaxDynamicSharedMemorySize, SMEM_SZ);
    prep_kernel<<<PREP_BLOCKS, 256>>>(W1, gamma, beta, W2, b2);
    head_kernel<<<PGRID, 512, SMEM_SZ>>>(hf, w_q, pi, stats, po, b1, out);
    (void)in_sizes; (void)n_in; (void)out_size;
}

// round 12
// speedup vs baseline: 1.1359x; 1.1359x over previous
#include <cuda_runtime.h>
#include <cuda_bf16.h>
#include <cstdint>

#define H_HOPS   100000
#define MAX_PI   8
#define D        128
#define D_FF     512
#define TT       64
#define LN_EPS   1e-5f
#define TILE_M   128
#define NCHUNK   8
#define PREP_BLOCKS 64

// ---- smem map (bytes) ----
#define XS_HI   0u            /* 128 x 136 bf16 = 34816 ; reused as f32 reduce buf */
#define XS_LO   34816u
#define BUF0    69632u
#define BUFSZ   53248u        /* W1H 17408 | W1L 17408 | WGH 9216 | WGL 9216 */
#define W1L_OFF 17408u
#define WGH_OFF 34816u
#define WGL_OFF 44032u
#define B1S     176128u       /* 512 f32 */
#define USOFF   178176u       /* 64 f32 */
#define VSOFF   178432u
#define SRED    178688u       /* 2 x 128 f32 */
#define QRED    179712u       /* 2 x 128 f32 */
#define MB0     180736u
#define MB1     180744u
#define SMEM_SZ 180768u

#define RSTRIDE 66            /* f32 stride of reduce buffer */

// ---- device scratch (weights only) ----
__device__ __align__(16) __nv_bfloat16 g_B1hi[NCHUNK * 64 * 136];
__device__ __align__(16) __nv_bfloat16 g_B1lo[NCHUNK * 64 * 136];
__device__ __align__(16) __nv_bfloat16 g_B2hi[NCHUNK * 64 * 72];
__device__ __align__(16) __nv_bfloat16 g_B2lo[NCHUNK * 64 * 72];
__device__ float g_u4[4 * TT];
__device__ float g_v4[4 * TT];

// ---- helpers ----
__device__ __forceinline__ unsigned smem_u32(const void* p) {
    return (unsigned)__cvta_generic_to_shared(p);
}
__device__ __forceinline__ uint32_t elect_one() {
    uint32_t p;
    asm volatile("{\n\t.reg .pred q;\n\telect.sync _|q, 0xFFFFFFFF;\n\t"
                 "selp.b32 %0, 1, 0, q;\n\t}" : "=r"(p));
    return p;
}
__device__ __forceinline__ unsigned cvt_bf16x2(float hi, float lo) {
    unsigned r;
    asm("cvt.rn.bf16x2.f32 %0, %1, %2;" : "=r"(r) : "f"(hi), "f"(lo));
    return r;
}
__device__ __forceinline__ float bf_lo(unsigned w) { return __uint_as_float(w << 16); }
__device__ __forceinline__ float bf_hi(unsigned w) { return __uint_as_float(w & 0xffff0000u); }
__device__ __forceinline__ void sts64(unsigned a, unsigned u0, unsigned u1) {
    asm volatile("st.shared.v2.b32 [%0], {%1, %2};" :: "r"(a), "r"(u0), "r"(u1) : "memory");
}
__device__ __forceinline__ void ldsm_x4(unsigned* r, unsigned a) {
    asm volatile("ldmatrix.sync.aligned.m8n8.x4.shared.b16 {%0,%1,%2,%3}, [%4];"
                 : "=r"(r[0]), "=r"(r[1]), "=r"(r[2]), "=r"(r[3]) : "r"(a));
}
__device__ __forceinline__ void ldsm_x2(unsigned* r, unsigned a) {
    asm volatile("ldmatrix.sync.aligned.m8n8.x2.shared.b16 {%0,%1}, [%2];"
                 : "=r"(r[0]), "=r"(r[1]) : "r"(a));
}
__device__ __forceinline__ void mma16816(float* d, const unsigned* a,
                                         unsigned b0, unsigned b1) {
    asm volatile(
        "mma.sync.aligned.m16n8k16.row.col.f32.bf16.bf16.f32 "
        "{%0,%1,%2,%3}, {%4,%5,%6,%7}, {%8,%9}, {%0,%1,%2,%3};"
        : "+f"(d[0]), "+f"(d[1]), "+f"(d[2]), "+f"(d[3])
        : "r"(a[0]), "r"(a[1]), "r"(a[2]), "r"(a[3]), "r"(b0), "r"(b1));
}

#define MBAR_INIT(a, c) \
    asm volatile("mbarrier.init.shared.b64 [%0], %1;" :: "r"(a), "r"(c) : "memory")
#define MBAR_EXPECT(a, b) \
    asm volatile("mbarrier.arrive.expect_tx.shared.b64 _, [%0], %1;" :: "r"(a), "r"(b) : "memory")
#define MBAR_WAIT(a, par) do {                                                  \
    asm volatile("{\n\t.reg .pred P1;\n\t"                                      \
        "WL_%=:\n\t"                                                            \
        "mbarrier.try_wait.parity.acquire.cta.shared::cta.b64 P1, [%0], %1, 0x989680;\n\t" \
        "@P1 bra.uni WD_%=;\n\tbra.uni WL_%=;\n\tWD_%=:\n\t}"                   \
        :: "r"(a), "r"(par) : "memory");                                        \
} while (0)
#define BULK_G2S(d, s, b, m) \
    asm volatile("cp.async.bulk.shared::cluster.global.mbarrier::complete_tx::bytes " \
                 "[%0], [%1], %2, [%3];" :: "r"(d), "l"(s), "r"(b), "r"(m) : "memory")

// ==================== prep: weight images + folded LN (4-way u/v) ====================
__global__ __launch_bounds__(256)
void prep_kernel(const float* __restrict__ W1, const float* __restrict__ gamma,
                 const float* __restrict__ beta, const float* __restrict__ W2,
                 const float* __restrict__ b2) {
    __shared__ float pu[256], pv[256];
    int g = blockIdx.x * 256 + threadIdx.x, gs = PREP_BLOCKS * 256;
    for (int i = g; i < D * D_FF; i += gs) {
        int k = i >> 9, n = i & 511;
        float val = W1[i];
        __nv_bfloat16 h = __float2bfloat16(val);
        __nv_bfloat16 lo = __float2bfloat16(val - __bfloat162float(h));
        int idx = (n >> 6) * (64 * 136) + (n & 63) * 136 + k;
        g_B1hi[idx] = h; g_B1lo[idx] = lo;
    }
    for (int i = g; i < D_FF * TT; i += gs) {
        int kf = i >> 6, n = i & 63;
        float val = gamma[kf] * W2[i];
        __nv_bfloat16 h = __float2bfloat16(val);
        __nv_bfloat16 lo = __float2bfloat16(val - __bfloat162float(h));
        int idx = (kf >> 6) * (64 * 72) + n * 72 + (kf & 63);
        g_B2hi[idx] = h; g_B2lo[idx] = lo;
    }
    if (blockIdx.x < 4) {
        int t = threadIdx.x & 63, sub = threadIdx.x >> 6;  // 4 subs x 32 c
        int c0 = blockIdx.x * 128 + sub * 32;
        float u = 0.f, v = 0.f;
        for (int c = c0; c < c0 + 32; c++) {
            float w2 = W2[c * TT + t];
            u += gamma[c] * w2; v += beta[c] * w2;
        }
        pu[threadIdx.x] = u; pv[threadIdx.x] = v;
        __syncthreads();
        if (threadIdx.x < 64) {
            float su = pu[t] + pu[64 + t] + pu[128 + t] + pu[192 + t];
            float sv = pv[t] + pv[64 + t] + pv[128 + t] + pv[192 + t];
            g_u4[blockIdx.x * 64 + t] = su;
            g_v4[blockIdx.x * 64 + t] = sv + (blockIdx.x == 0 ? b2[t] : 0.f);
        }
    }
}

// pool one hop row (warp-collective), two-pass to keep registers low
__device__ __forceinline__ float4 pool_row(
    const float* __restrict__ hf, float4 wq,
    const int* __restrict__ pi, const int* __restrict__ stats,
    const int* __restrict__ po, int gr, int d0) {
    int idxs[MAX_PI + 1]; bool ok[MAX_PI + 1]; float sc[MAX_PI + 1];
    #pragma unroll
    for (int p = 0; p < MAX_PI; p++) {
        idxs[p] = pi[gr * MAX_PI + p];
        ok[p] = (stats[gr * MAX_PI + p] != -1);
    }
    idxs[MAX_PI] = po[gr]; ok[MAX_PI] = true;
    #pragma unroll
    for (int p = 0; p <= MAX_PI; p++) {
        float4 t = *reinterpret_cast<const float4*>(hf + (long long)idxs[p] * D + d0);
        float s = t.x * wq.x + t.y * wq.y + t.z * wq.z + t.w * wq.w;
        #pragma unroll
        for (int o = 16; o; o >>= 1) s += __shfl_xor_sync(0xffffffffu, s, o);
        sc[p] = s * 0.08838834764831845f;
    }
    float m = -1e30f;
    #pragma unroll
    for (int p = 0; p <= MAX_PI; p++) if (ok[p] && sc[p] > m) m = sc[p];
    float den = 0.f; float e[MAX_PI + 1];
    #pragma unroll
    for (int p = 0; p <= MAX_PI; p++) {
        e[p] = ok[p] ? __expf(sc[p] - m) : 0.f;
        den += e[p];
    }
    float inv = 1.f / den;
    float4 acc = make_float4(0.f, 0.f, 0.f, 0.f);
    #pragma unroll
    for (int p = 0; p <= MAX_PI; p++) {
        const float* ap = hf + (long long)idxs[p] * D + d0;
        float4 t;
        asm volatile("ld.global.nc.v4.f32 {%0,%1,%2,%3}, [%4];"
                     : "=f"(t.x), "=f"(t.y), "=f"(t.z), "=f"(t.w) : "l"(ap));
        acc.x = fmaf(e[p], t.x, acc.x); acc.y = fmaf(e[p], t.y, acc.y);
        acc.z = fmaf(e[p], t.z, acc.z); acc.w = fmaf(e[p], t.w, acc.w);
    }
    acc.x *= inv; acc.y *= inv; acc.z *= inv; acc.w *= inv;
    return acc;
}

// ====== fused head: pooled prologue (unroll 2) + 16 warps N-split mma.sync ======
__global__ __launch_bounds__(512, 1)
void head_kernel(const float* __restrict__ hf, const float* __restrict__ w_q,
                 const int* __restrict__ pi, const int* __restrict__ stats,
                 const int* __restrict__ po,
                 const float* __restrict__ b1, float* __restrict__ out) {
    extern __shared__ char smem[];
    const unsigned sb = smem_u32(smem);
    int tid = threadIdx.x, w = tid >> 5, lane = tid & 31;
    int wm = w & 7, g2 = w >> 3;          // row-group / N-half
    int grp = lane >> 2, q = lane & 3;
    int LL = lane & 15;
    int row0 = blockIdx.x * TILE_M, m0 = wm * 16;

    if (tid == 0) { MBAR_INIT(sb + MB0, 1); MBAR_INIT(sb + MB1, 1); }
    __syncthreads();

    if (w == 0 && elect_one()) {          // prefetch chunks 0,1
        MBAR_EXPECT(sb + MB0, BUFSZ);
        BULK_G2S(sb + BUF0,           (const void*)(g_B1hi), 17408u, sb + MB0);
        BULK_G2S(sb + BUF0 + W1L_OFF, (const void*)(g_B1lo), 17408u, sb + MB0);
        BULK_G2S(sb + BUF0 + WGH_OFF, (const void*)(g_B2hi), 9216u,  sb + MB0);
        BULK_G2S(sb + BUF0 + WGL_OFF, (const void*)(g_B2lo), 9216u,  sb + MB0);
        MBAR_EXPECT(sb + MB1, BUFSZ);
        BULK_G2S(sb + BUF0 + BUFSZ,            (const void*)(g_B1hi + 8704), 17408u, sb + MB1);
        BULK_G2S(sb + BUF0 + BUFSZ + W1L_OFF,  (const void*)(g_B1lo + 8704), 17408u, sb + MB1);
        BULK_G2S(sb + BUF0 + BUFSZ + WGH_OFF,  (const void*)(g_B2hi + 4608), 9216u,  sb + MB1);
        BULK_G2S(sb + BUF0 + BUFSZ + WGL_OFF,  (const void*)(g_B2lo + 4608), 9216u,  sb + MB1);
    }

    float* b1s = (float*)(smem + B1S);
    for (int i = tid; i < D_FF; i += 512) b1s[i] = b1[i];
    if (tid < TT) {
        ((float*)(smem + USOFF))[tid] =
            g_u4[tid] + g_u4[64 + tid] + g_u4[128 + tid] + g_u4[192 + tid];
        ((float*)(smem + VSOFF))[tid] =
            g_v4[tid] + g_v4[64 + tid] + g_v4[128 + tid] + g_v4[192 + tid];
    }

    // ---- pooled prologue: warp w pools rows row0+8w..+7 (2 rows in flight) ----
    {
        int d0 = lane * 4;
        float4 wq = *reinterpret_cast<const float4*>(w_q + d0);
        #pragma unroll 2
        for (int i = 0; i < 8; i++) {
            int r = w * 8 + i, gr = row0 + r;
            int grc = (gr < H_HOPS) ? gr : (H_HOPS - 1);
            float4 acc = pool_row(hf, wq, pi, stats, po, grc, d0);
            if (gr >= H_HOPS) acc = make_float4(0.f, 0.f, 0.f, 0.f);
            unsigned h0 = cvt_bf16x2(acc.y, acc.x), h1 = cvt_bf16x2(acc.w, acc.z);
            unsigned a = sb + XS_HI + (unsigned)(r * 272 + d0 * 2);
            sts64(a, h0, h1);
            float e0 = acc.x - bf_lo(h0), e1 = acc.y - bf_hi(h0);
            float e2 = acc.z - bf_lo(h1), e3 = acc.w - bf_hi(h1);
            sts64(a + XS_LO, cvt_bf16x2(e1, e0), cvt_bf16x2(e3, e2));
        }
    }
    __syncthreads();

    float acc2[32];
    #pragma unroll
    for (int i = 0; i < 32; i++) acc2[i] = 0.f;
    float s0 = 0.f, q0 = 0.f, s1 = 0.f, q1 = 0.f;
    const unsigned abase  = sb + XS_HI + (unsigned)((m0 + LL) * 272 + (lane >> 4) * 16);
    const unsigned bgeom1 = (unsigned)((LL & 7) * 272 + ((LL >> 3) & 1) * 16);
    const unsigned bgeom2 = (unsigned)((LL & 7) * 144 + ((LL >> 3) & 1) * 16);

    for (int c = 0; c < NCHUNK; c++) {
        unsigned bb_ = sb + BUF0 + (unsigned)((c & 1) * BUFSZ);
        MBAR_WAIT(sb + MB0 + 8u * (unsigned)(c & 1), (unsigned)((c >> 1) & 1));

        float acc1[16];
        #pragma unroll
        for (int i = 0; i < 16; i++) acc1[i] = 0.f;
        unsigned b1base = bb_ + bgeom1 + (unsigned)(g2 * 4 * 2176);

        #pragma unroll
        for (int s = 0; s < 8; s++) {
            unsigned Ah[4], Al[4];
            ldsm_x4(Ah, abase + (unsigned)(s * 32));
            ldsm_x4(Al, abase + XS_LO + (unsigned)(s * 32));
            #pragma unroll
            for (int j2 = 0; j2 < 4; j2++) {
                unsigned Bh[2], Bl[2];
                unsigned ba = b1base + (unsigned)(j2 * 2176 + s * 32);
                ldsm_x2(Bh, ba);
                ldsm_x2(Bl, ba + W1L_OFF);
                mma16816(acc1 + 4 * j2, Ah, Bh[0], Bh[1]);
                mma16816(acc1 + 4 * j2, Ah, Bl[0], Bl[1]);
                mma16816(acc1 + 4 * j2, Al, Bh[0], Bh[1]);
            }
        }

        // bias + relu + LN partials + register repack (our 32-col k-slice)
        unsigned A2h[8], A2l[8];
        #pragma unroll
        for (int j2 = 0; j2 < 4; j2++) {
            int col = c * 64 + g2 * 32 + 8 * j2 + 2 * q;
            float2 bb = *(const float2*)(smem + B1S + col * 4);
            float h0 = fmaxf(acc1[4 * j2 + 0] + bb.x, 0.f);
            float h1 = fmaxf(acc1[4 * j2 + 1] + bb.y, 0.f);
            float h2 = fmaxf(acc1[4 * j2 + 2] + bb.x, 0.f);
            float h3 = fmaxf(acc1[4 * j2 + 3] + bb.y, 0.f);
            s0 += h0 + h1; q0 = fmaf(h0, h0, fmaf(h1, h1, q0));
            s1 += h2 + h3; q1 = fmaf(h2, h2, fmaf(h3, h3, q1));
            unsigned p0 = cvt_bf16x2(h1, h0), p1 = cvt_bf16x2(h3, h2);
            int bi = (j2 >> 1) * 4 + (j2 & 1) * 2;
            A2h[bi] = p0; A2h[bi + 1] = p1;
            float e0 = h0 - bf_lo(p0), e1 = h1 - bf_hi(p0);
            float e2 = h2 - bf_lo(p1), e3 = h3 - bf_hi(p1);
            A2l[bi] = cvt_bf16x2(e1, e0); A2l[bi + 1] = cvt_bf16x2(e3, e2);
        }

        // GEMM2 partial over our 32-wide k slice
        unsigned g2base = bb_ + WGH_OFF + bgeom2;
        #pragma unroll
        for (int t = 0; t < 2; t++) {
            #pragma unroll
            for (int jn = 0; jn < 8; jn++) {
                unsigned Bh[2], Bl[2];
                unsigned ba = g2base + (unsigned)(jn * 1152 + (g2 * 2 + t) * 32);
                ldsm_x2(Bh, ba);
                ldsm_x2(Bl, ba + 9216);
                mma16816(acc2 + 4 * jn, A2h + 4 * t, Bh[0], Bh[1]);
                mma16816(acc2 + 4 * jn, A2h + 4 * t, Bl[0], Bl[1]);
                mma16816(acc2 + 4 * jn, A2l + 4 * t, Bh[0], Bh[1]);
            }
        }
        __syncthreads();
        if (c < NCHUNK - 2 && w == 0 && elect_one()) {
            int nc = c + 2;
            unsigned mb = sb + MB0 + 8u * (unsigned)(c & 1);
            MBAR_EXPECT(mb, BUFSZ);
            BULK_G2S(bb_,           (const void*)(g_B1hi + nc * 8704), 17408u, mb);
            BULK_G2S(bb_ + W1L_OFF, (const void*)(g_B1lo + nc * 8704), 17408u, mb);
            BULK_G2S(bb_ + WGH_OFF, (const void*)(g_B2hi + nc * 4608), 9216u,  mb);
            BULK_G2S(bb_ + WGL_OFF, (const void*)(g_B2lo + nc * 4608), 9216u,  mb);
        }
    }

    // LN partials: reduce over 4 q-lanes, publish per (half, row)
    s0 += __shfl_xor_sync(0xffffffffu, s0, 1); s0 += __shfl_xor_sync(0xffffffffu, s0, 2);
    q0 += __shfl_xor_sync(0xffffffffu, q0, 1); q0 += __shfl_xor_sync(0xffffffffu, q0, 2);
    s1 += __shfl_xor_sync(0xffffffffu, s1, 1); s1 += __shfl_xor_sync(0xffffffffu, s1, 2);
    q1 += __shfl_xor_sync(0xffffffffu, q1, 1); q1 += __shfl_xor_sync(0xffffffffu, q1, 2);
    float* sred = (float*)(smem + SRED);
    float* qred = (float*)(smem + QRED);
    if (q == 0) {
        sred[g2 * 128 + m0 + grp]     = s0;  qred[g2 * 128 + m0 + grp]     = q0;
        sred[g2 * 128 + m0 + grp + 8] = s1;  qred[g2 * 128 + m0 + grp + 8] = q1;
    }
    __syncthreads();

    // cross-half acc2 reduction through smem (reuse XS region)
    float* red = (float*)(smem + XS_HI);
    if (g2 == 1) {
        #pragma unroll
        for (int jn = 0; jn < 8; jn++) {
            int col = 8 * jn + 2 * q;
            *(float2*)(red + (m0 + grp) * RSTRIDE + col) =
                make_float2(acc2[4 * jn + 0], acc2[4 * jn + 1]);
            *(float2*)(red + (m0 + grp + 8) * RSTRIDE + col) =
                make_float2(acc2[4 * jn + 2], acc2[4 * jn + 3]);
        }
    }
    __syncthreads();
    if (g2 == 0) {
        float sA = sred[m0 + grp] + sred[128 + m0 + grp];
        float qA = qred[m0 + grp] + qred[128 + m0 + grp];
        float sB = sred[m0 + grp + 8] + sred[128 + m0 + grp + 8];
        float qB = qred[m0 + grp + 8] + qred[128 + m0 + grp + 8];
        float muA = sA * (1.f / D_FF), muB = sB * (1.f / D_FF);
        float rsA = rsqrtf(qA * (1.f / D_FF) - muA * muA + LN_EPS);
        float rsB = rsqrtf(qB * (1.f / D_FF) - muB * muB + LN_EPS);
        int ra = row0 + m0 + grp, rb = ra + 8;
        #pragma unroll
        for (int jn = 0; jn < 8; jn++) {
            int col = 8 * jn + 2 * q;
            float2 uu = *(const float2*)(smem + USOFF + col * 4);
            float2 vv = *(const float2*)(smem + VSOFF + col * 4);
            float2 pA = *(const float2*)(red + (m0 + grp) * RSTRIDE + col);
            float2 pB = *(const float2*)(red + (m0 + grp + 8) * RSTRIDE + col);
            if (ra < H_HOPS) {
                float2 o;
                o.x = rsA * (acc2[4 * jn + 0] + pA.x - muA * uu.x) + vv.x;
                o.y = rsA * (acc2[4 * jn + 1] + pA.y - muA * uu.y) + vv.y;
                *(float2*)(out + (size_t)ra * TT + col) = o;
            }
            if (rb < H_HOPS) {
                float2 o;
                o.x = rsB * (acc2[4 * jn + 2] + pB.x - muB * uu.x) + vv.x;
                o.y = rsB * (acc2[4 * jn + 3] + pB.y - muB * uu.y) + vv.y;
                *(float2*)(out + (size_t)rb * TT + col) = o;
            }
        }
    }
}

extern "C" void kernel_launch(void* const* d_in, const int* in_sizes, int n_in,
                              void* d_out, int out_size) {
    const float* hf    = (const float*)d_in[0];
    const float* w_q   = (const float*)d_in[1];
    const float* W1    = (const float*)d_in[2];
    const float* b1    = (const float*)d_in[3];
    const float* gamma = (const float*)d_in[4];
    const float* beta  = (const float*)d_in[5];
    const float* W2    = (const float*)d_in[6];
    const float* b2    = (const float*)d_in[7];
    const int* pi      = (const int*)d_in[8];
    const int* stats   = (const int*)d_in[9];
    const int* po      = (const int*)d_in[10];
    float* out = (float*)d_out;

    cudaFuncSetAttribute(head_kernel,
                         cudaFuncAttributeMaxDynamicSharedMemorySize, SMEM_SZ);
    prep_kernel<<<PREP_BLOCKS, 256>>>(W1, gamma, beta, W2, b2);
    head_kernel<<<(H_HOPS + TILE_M - 1) / TILE_M, 512, SMEM_SZ>>>(
        hf, w_q, pi, stats, po, b1, out);
    (void)in_sizes; (void)n_in; (void)out_size;
}